// round 2
// baseline (speedup 1.0000x reference)
#include <cuda_runtime.h>
#include <cstdint>

// RBF kernel, D=1 degenerate case:
//   out[b,i,j] = exp( -(x1[b,i] - x2[b,j])^2 / (2*scale^2) )
// B=4, N1=N2=8192. Output = 268,435,456 fp32 = 1.07 GB -> store-bandwidth bound.
//
// Tiling: each block covers TI=8 rows (i) x TJ=1024 cols (j).
//  - 256 threads, each holds one float4 of x2 in registers.
//  - x1 values broadcast-read 8x per block (L1 hit).
//  - stores are STG.E.128, fully coalesced.
// This amortizes x2 L2 reads 8x so L2 traffic (~1.2 GB total) stays under the
// HBM store floor (~134 us at 8 TB/s).

static constexpr int B  = 4;
static constexpr int N1 = 8192;
static constexpr int N2 = 8192;
static constexpr int TI = 8;
static constexpr int TJ = 1024;   // 256 threads * float4

__global__ __launch_bounds__(256, 8)
void rbf_kernel(const float* __restrict__ x1,
                const float* __restrict__ x2,
                const float* __restrict__ scale,
                float* __restrict__ out)
{
    const int tid = threadIdx.x;
    const int jb  = blockIdx.x;        // 0..N2/TJ-1  (8)
    const int it  = blockIdx.y;        // 0..N1/TI-1  (1024)
    const int b   = blockIdx.z;        // 0..B-1

    const int j  = jb * TJ + tid * 4;
    const int i0 = it * TI;

    // x2 chunk for this thread (registers)
    const float4 v2 = *reinterpret_cast<const float4*>(x2 + (size_t)b * N2 + j);

    const float s = scale[0];
    // exp(-d/(2 s^2)) ; fold constant
    const float c = -0.5f / (s * s);

    const float* x1b = x1 + (size_t)b * N1 + i0;
    float* outb = out + ((size_t)b * N1 + i0) * (size_t)N2 + j;

#pragma unroll
    for (int r = 0; r < TI; ++r) {
        const float a = __ldg(x1b + r);   // uniform across block, L1-hot
        float dx0 = a - v2.x;
        float dx1 = a - v2.y;
        float dx2 = a - v2.z;
        float dx3 = a - v2.w;
        float4 o;
        o.x = __expf(c * dx0 * dx0);
        o.y = __expf(c * dx1 * dx1);
        o.z = __expf(c * dx2 * dx2);
        o.w = __expf(c * dx3 * dx3);
        *reinterpret_cast<float4*>(outb + (size_t)r * N2) = o;
    }
}

extern "C" void kernel_launch(void* const* d_in, const int* in_sizes, int n_in,
                              void* d_out, int out_size)
{
    const float* x1    = (const float*)d_in[0];
    const float* x2    = (const float*)d_in[1];
    const float* scale = (const float*)d_in[2];
    float* out         = (float*)d_out;

    dim3 grid(N2 / TJ, N1 / TI, B);   // (8, 1024, 4)
    rbf_kernel<<<grid, 256>>>(x1, x2, scale, out);
}